// round 1
// baseline (speedup 1.0000x reference)
#include <cuda_runtime.h>

#define GRID_NUM 7
#define CELLS_PER_IMG 49
#define IMG_SIZE 448.0f
#define GRID_SIZE 64.0f
#define LAMBDA_COORD 5.0f
#define LAMBDA_NOOBJ 0.1f
#define EPSF 1e-12f

__device__ double g_acc;

__global__ void zero_acc_kernel() {
    g_acc = 0.0;
}

__device__ __forceinline__ float iou_f(float bx, float by, float bw, float bh,
                                       float tx, float ty, float tw, float th,
                                       float gi, float gj) {
    // prediction box
    float cx_p = bx * GRID_SIZE + gj * GRID_SIZE;
    float cy_p = by * GRID_SIZE + gi * GRID_SIZE;
    float w_p = bw * IMG_SIZE;
    float h_p = bh * IMG_SIZE;
    float x0p = cx_p - w_p * 0.5f, x1p = cx_p + w_p * 0.5f;
    float y0p = cy_p - h_p * 0.5f, y1p = cy_p + h_p * 0.5f;
    // true box (preserving the reference's y1_t = cy_t + w_t typo)
    float cx_t = tx * GRID_SIZE + gj * GRID_SIZE;
    float cy_t = ty * GRID_SIZE + gi * GRID_SIZE;
    float w_t = tw * IMG_SIZE;
    float h_t = th * IMG_SIZE;
    float x0t = cx_t - w_t * 0.5f, x1t = cx_t + w_t * 0.5f;
    float y0t = cy_t - h_t * 0.5f;
    float y1t = cy_t + w_t * 0.5f;   // TYPO kept: uses w_t not h_t
    float ux0 = fmaxf(x0p, x0t);
    float ux1 = fminf(x1p, x1t);
    float uy0 = fmaxf(y0p, y0t);
    float uy1 = fminf(y1p, y1t);
    bool valid = (ux0 < ux1) && (uy0 < uy1);
    float area_u = (ux1 - ux0) * (uy1 - uy0);
    float area_p = (x1p - x0p) * (y1p - y0p);
    float area_t = (x1t - x0t) * (y1t - y0t);
    float res = area_u / (area_p + area_t - area_u + EPSF);
    return valid ? res : 0.0f;
}

__global__ void __launch_bounds__(256)
yolo_loss_kernel(const float* __restrict__ y_pre,
                 const float* __restrict__ y_true,
                 int n_cells) {
    int idx = blockIdx.x * blockDim.x + threadIdx.x;
    float local = 0.0f;
    if (idx < n_cells) {
        int g = idx % CELLS_PER_IMG;
        float gi = (float)(g / GRID_NUM);
        float gj = (float)(g % GRID_NUM);

        // y_pre cell: 10 floats, 40-byte stride -> 8B aligned -> float2 loads
        const float2* p = (const float2*)(y_pre + (size_t)idx * 10);
        float2 p01 = p[0];  // [0],[1]
        float2 p23 = p[1];  // [2],[3]
        float2 p45 = p[2];  // [4],[5]
        float2 p67 = p[3];  // [6],[7]
        float2 p89 = p[4];  // [8],[9]

        const float* t = y_true + (size_t)idx * 5;
        float t0 = t[0], t1 = t[1], t2 = t[2], t3 = t[3], t4 = t[4];

        // box0 = pre[0:4], box1 = pre[5:9]
        float iou0 = iou_f(p01.x, p01.y, p23.x, p23.y, t0, t1, t2, t3, gi, gj);
        float iou1 = iou_f(p45.y, p67.x, p67.y, p89.x, t0, t1, t2, t3, gi, gj);

        bool obj = (t4 == 1.0f);
        bool c0 = iou0 > iou1;

        if (obj) {
            // confidence (object)
            float conf_pre = c0 ? p45.x : p89.y;   // pre[4] : pre[9]
            float conf_true = c0 ? iou0 : iou1;
            float dc = conf_pre - conf_true;
            local = dc * dc;
            // coordinate
            float xb = c0 ? p01.x : p45.y;         // pre[0] : pre[5]
            float yb = c0 ? p01.y : p67.x;         // pre[1] : pre[6]
            float dx = xb - t0;
            float dy = yb - t1;
            local += LAMBDA_COORD * (dx * dx + dy * dy);
            // scale (sqrt of w/h)
            float wb = fmaxf(c0 ? p23.x : p67.y, EPSF);  // pre[2] : pre[7]
            float hb = fmaxf(c0 ? p23.y : p89.x, EPSF);  // pre[3] : pre[8]
            float wt = fmaxf(t2, EPSF);
            float ht = fmaxf(t3, EPSF);
            float dw = sqrtf(wb) - sqrtf(wt);
            float dh = sqrtf(hb) - sqrtf(ht);
            local += LAMBDA_COORD * (dw * dw + dh * dh);
        } else {
            // no-object confidence penalty on both boxes
            local = LAMBDA_NOOBJ * (p45.x * p45.x + p89.y * p89.y);
        }
    }

    // ---- block reduction ----
    // warp reduce
    #pragma unroll
    for (int off = 16; off > 0; off >>= 1)
        local += __shfl_down_sync(0xFFFFFFFFu, local, off);

    __shared__ float warp_sums[8];  // 256 threads = 8 warps
    int lane = threadIdx.x & 31;
    int wid = threadIdx.x >> 5;
    if (lane == 0) warp_sums[wid] = local;
    __syncthreads();

    if (wid == 0) {
        float v = (lane < 8) ? warp_sums[lane] : 0.0f;
        #pragma unroll
        for (int off = 4; off > 0; off >>= 1)
            v += __shfl_down_sync(0xFFFFFFFFu, v, off);
        if (lane == 0)
            atomicAdd(&g_acc, (double)v);
    }
}

__global__ void finalize_kernel(float* out, float inv_b) {
    out[0] = (float)(g_acc * (double)inv_b);
}

extern "C" void kernel_launch(void* const* d_in, const int* in_sizes, int n_in,
                              void* d_out, int out_size) {
    const float* y_pre = (const float*)d_in[0];
    const float* y_true = (const float*)d_in[1];
    float* out = (float*)d_out;

    int n_cells = in_sizes[1] / 5;           // B * 49
    int B = n_cells / CELLS_PER_IMG;

    zero_acc_kernel<<<1, 1>>>();

    int threads = 256;
    int blocks = (n_cells + threads - 1) / threads;
    yolo_loss_kernel<<<blocks, threads>>>(y_pre, y_true, n_cells);

    finalize_kernel<<<1, 1>>>(out, 1.0f / (float)B);
}